// round 1
// baseline (speedup 1.0000x reference)
#include <cuda_runtime.h>

#define RES 128
#define N_COMPS 16   // DEGREE^2
#define CH 3
#define COEFS_PER_CELL (N_COMPS * CH)   // 48 floats = 192 bytes

__global__ __launch_bounds__(256)
void irradiance_kernel(const float* __restrict__ coeff,
                       const float* __restrict__ aabb,
                       const float* __restrict__ points,
                       const float* __restrict__ normals,
                       float* __restrict__ out,
                       int n)
{
    int i = blockIdx.x * blockDim.x + threadIdx.x;
    if (i >= n) return;

    // ---- load point & normal ----
    float px = points[3 * i + 0];
    float py = points[3 * i + 1];
    float pz = points[3 * i + 2];
    float nx = normals[3 * i + 0];
    float ny = normals[3 * i + 1];
    float nz = normals[3 * i + 2];

    // ---- aabb (tiny, L1/L2 resident) ----
    float amin0 = __ldg(&aabb[0]);
    float amin1 = __ldg(&aabb[1]);
    float amin2 = __ldg(&aabb[2]);
    float amax0 = __ldg(&aabb[3]);
    float amax1 = __ldg(&aabb[4]);
    float amax2 = __ldg(&aabb[5]);

    const float RM1 = (float)(RES - 1);

    // grid coords, reference semantics: g = clip((p-amin)/(amax-amin)*(R-1), 0, R-1)
    float gx = (px - amin0) / (amax0 - amin0) * RM1;
    float gy = (py - amin1) / (amax1 - amin1) * RM1;
    float gz = (pz - amin2) / (amax2 - amin2) * RM1;
    gx = fminf(fmaxf(gx, 0.0f), RM1);
    gy = fminf(fmaxf(gy, 0.0f), RM1);
    gz = fminf(fmaxf(gz, 0.0f), RM1);

    int ix = min((int)floorf(gx), RES - 2);
    int iy = min((int)floorf(gy), RES - 2);
    int iz = min((int)floorf(gz), RES - 2);
    // floor of clipped g is >= 0 already
    float fx = gx - (float)ix;
    float fy = gy - (float)iy;
    float fz = gz - (float)iz;

    // ---- SH components (degree 4, 16 comps), exact reference constants ----
    float comp[N_COMPS];
    {
        float x = nx, y = ny, z = nz;
        float xx = x * x, yy = y * y, zz = z * z;
        float xy = x * y, yz = y * z, xz = x * z;
        comp[0] = 0.28209479177387814f;
        comp[1] = -0.4886025119029199f * y;
        comp[2] =  0.4886025119029199f * z;
        comp[3] = -0.4886025119029199f * x;
        comp[4] =  1.0925484305920792f * xy;
        comp[5] = -1.0925484305920792f * yz;
        comp[6] =  0.31539156525252005f * (2.0f * zz - xx - yy);
        comp[7] = -1.0925484305920792f * xz;
        comp[8] =  0.5462742152960396f * (xx - yy);
        comp[9]  = -0.5900435899266435f * y * (3.0f * xx - yy);
        comp[10] =  2.890611442640554f  * xy * z;
        comp[11] = -0.4570457994644658f * y * (4.0f * zz - xx - yy);
        comp[12] =  0.3731763325901154f * z * (2.0f * zz - 3.0f * xx - 3.0f * yy);
        comp[13] = -0.4570457994644658f * x * (4.0f * zz - xx - yy);
        comp[14] =  1.445305721320277f  * z * (xx - yy);
        comp[15] = -0.5900435899266435f * x * (xx - 3.0f * yy);
    }

    float wx[2] = {1.0f - fx, fx};
    float wy[2] = {1.0f - fy, fy};
    float wz[2] = {1.0f - fz, fz};

    float acc0 = 0.0f, acc1 = 0.0f, acc2 = 0.0f;

    #pragma unroll
    for (int dx = 0; dx < 2; dx++) {
        #pragma unroll
        for (int dy = 0; dy < 2; dy++) {
            // z-pair is contiguous: 2 * 192B = 384B
            long cell = (((long)(ix + dx) * RES) + (iy + dy)) * RES + iz;
            const float4* p4 = (const float4*)(coeff + cell * COEFS_PER_CELL);
            float wxy = wx[dx] * wy[dy];
            #pragma unroll
            for (int dz = 0; dz < 2; dz++) {
                float w = wxy * wz[dz];
                float4 buf[12];
                #pragma unroll
                for (int j = 0; j < 12; j++) {
                    buf[j] = p4[dz * 12 + j];
                }
                const float* v = (const float*)buf;
                float s0 = 0.0f, s1 = 0.0f, s2 = 0.0f;
                #pragma unroll
                for (int k = 0; k < N_COMPS; k++) {
                    s0 = fmaf(comp[k], v[3 * k + 0], s0);
                    s1 = fmaf(comp[k], v[3 * k + 1], s1);
                    s2 = fmaf(comp[k], v[3 * k + 2], s2);
                }
                acc0 = fmaf(w, s0, acc0);
                acc1 = fmaf(w, s1, acc1);
                acc2 = fmaf(w, s2, acc2);
            }
        }
    }

    out[3 * i + 0] = fmaxf(acc0, 0.0f);
    out[3 * i + 1] = fmaxf(acc1, 0.0f);
    out[3 * i + 2] = fmaxf(acc2, 0.0f);
}

extern "C" void kernel_launch(void* const* d_in, const int* in_sizes, int n_in,
                              void* d_out, int out_size)
{
    const float* coeff   = (const float*)d_in[0];  // [128,128,128,16,3]
    const float* aabb    = (const float*)d_in[1];  // [6]
    const float* points  = (const float*)d_in[2];  // [N,3]
    const float* normals = (const float*)d_in[3];  // [N,3]
    float* out = (float*)d_out;                    // [N,3]

    int n = in_sizes[2] / 3;
    int block = 256;
    int grid = (n + block - 1) / block;
    irradiance_kernel<<<grid, block>>>(coeff, aabb, points, normals, out, n);
}

// round 2
// speedup vs baseline: 1.2076x; 1.2076x over previous
#include <cuda_runtime.h>

#define RES 128
#define N_COMPS 16
#define COEFS_PER_CELL 48   // 16 comps * 3 ch = 192 bytes

__global__ __launch_bounds__(256)
void irradiance_kernel(const float* __restrict__ coeff,
                       const float* __restrict__ aabb,
                       const float* __restrict__ points,
                       const float* __restrict__ normals,
                       float* __restrict__ out,
                       int n)
{
    int t = blockIdx.x * blockDim.x + threadIdx.x;
    int i = t >> 3;          // point index (8 threads per point)
    if (i >= n) return;
    int c  = t & 7;          // corner index
    int dx = (c >> 2) & 1;
    int dy = (c >> 1) & 1;
    int dz = c & 1;

    // ---- point & normal (broadcast across the 8-lane group via L1) ----
    float px = points[3 * i + 0];
    float py = points[3 * i + 1];
    float pz = points[3 * i + 2];
    float nx = normals[3 * i + 0];
    float ny = normals[3 * i + 1];
    float nz = normals[3 * i + 2];

    float amin0 = __ldg(&aabb[0]);
    float amin1 = __ldg(&aabb[1]);
    float amin2 = __ldg(&aabb[2]);
    float amax0 = __ldg(&aabb[3]);
    float amax1 = __ldg(&aabb[4]);
    float amax2 = __ldg(&aabb[5]);

    const float RM1 = (float)(RES - 1);

    float gx = (px - amin0) / (amax0 - amin0) * RM1;
    float gy = (py - amin1) / (amax1 - amin1) * RM1;
    float gz = (pz - amin2) / (amax2 - amin2) * RM1;
    gx = fminf(fmaxf(gx, 0.0f), RM1);
    gy = fminf(fmaxf(gy, 0.0f), RM1);
    gz = fminf(fmaxf(gz, 0.0f), RM1);

    int ix = min((int)floorf(gx), RES - 2);
    int iy = min((int)floorf(gy), RES - 2);
    int iz = min((int)floorf(gz), RES - 2);
    float fx = gx - (float)ix;
    float fy = gy - (float)iy;
    float fz = gz - (float)iz;

    // trilinear weight for this corner
    float w = (dx ? fx : 1.0f - fx) * (dy ? fy : 1.0f - fy) * (dz ? fz : 1.0f - fz);

    // ---- issue this corner's full 192B cell read as one burst of 12 LDG.128 ----
    long cell = (((long)(ix + dx) * RES) + (iy + dy)) * RES + (iz + dz);
    const float4* p4 = (const float4*)(coeff + cell * COEFS_PER_CELL);
    float4 buf[12];
    #pragma unroll
    for (int j = 0; j < 12; j++) {
        buf[j] = __ldcg(p4 + j);   // L2-only: no L1 reuse expected
    }

    // ---- SH components (degree 4), exact reference constants ----
    float comp[N_COMPS];
    {
        float x = nx, y = ny, z = nz;
        float xx = x * x, yy = y * y, zz = z * z;
        float xy = x * y, yz = y * z, xz = x * z;
        comp[0]  =  0.28209479177387814f;
        comp[1]  = -0.4886025119029199f * y;
        comp[2]  =  0.4886025119029199f * z;
        comp[3]  = -0.4886025119029199f * x;
        comp[4]  =  1.0925484305920792f * xy;
        comp[5]  = -1.0925484305920792f * yz;
        comp[6]  =  0.31539156525252005f * (2.0f * zz - xx - yy);
        comp[7]  = -1.0925484305920792f * xz;
        comp[8]  =  0.5462742152960396f * (xx - yy);
        comp[9]  = -0.5900435899266435f * y * (3.0f * xx - yy);
        comp[10] =  2.890611442640554f  * xy * z;
        comp[11] = -0.4570457994644658f * y * (4.0f * zz - xx - yy);
        comp[12] =  0.3731763325901154f * z * (2.0f * zz - 3.0f * xx - 3.0f * yy);
        comp[13] = -0.4570457994644658f * x * (4.0f * zz - xx - yy);
        comp[14] =  1.445305721320277f  * z * (xx - yy);
        comp[15] = -0.5900435899266435f * x * (xx - 3.0f * yy);
    }

    const float* v = (const float*)buf;
    float s0 = 0.0f, s1 = 0.0f, s2 = 0.0f;
    #pragma unroll
    for (int k = 0; k < N_COMPS; k++) {
        s0 = fmaf(comp[k], v[3 * k + 0], s0);
        s1 = fmaf(comp[k], v[3 * k + 1], s1);
        s2 = fmaf(comp[k], v[3 * k + 2], s2);
    }
    float a0 = w * s0;
    float a1 = w * s1;
    float a2 = w * s2;

    // ---- butterfly reduce over the 8 corner lanes ----
    #pragma unroll
    for (int off = 4; off > 0; off >>= 1) {
        a0 += __shfl_xor_sync(0xffffffffu, a0, off);
        a1 += __shfl_xor_sync(0xffffffffu, a1, off);
        a2 += __shfl_xor_sync(0xffffffffu, a2, off);
    }

    if (c == 0) {
        out[3 * i + 0] = fmaxf(a0, 0.0f);
        out[3 * i + 1] = fmaxf(a1, 0.0f);
        out[3 * i + 2] = fmaxf(a2, 0.0f);
    }
}

extern "C" void kernel_launch(void* const* d_in, const int* in_sizes, int n_in,
                              void* d_out, int out_size)
{
    const float* coeff   = (const float*)d_in[0];
    const float* aabb    = (const float*)d_in[1];
    const float* points  = (const float*)d_in[2];
    const float* normals = (const float*)d_in[3];
    float* out = (float*)d_out;

    int n = in_sizes[2] / 3;
    long total = (long)n * 8;
    int block = 256;
    long grid = (total + block - 1) / block;
    irradiance_kernel<<<(int)grid, block>>>(coeff, aabb, points, normals, out, n);
}

// round 3
// speedup vs baseline: 2.3131x; 1.9154x over previous
#include <cuda_runtime.h>

#define RES 128
#define N_COMPS 16
#define COEFS_PER_CELL 48   // 192 bytes

// Dot of this lane's 12 floats (positions F = 16j + 4S + q in the 48-float cell)
// against comp[F/3], accumulating into channel F%3. S is a literal -> all folds.
#define DOT4(S)                                                         \
    {                                                                   \
        _Pragma("unroll")                                               \
        for (int j = 0; j < 3; ++j) {                                   \
            _Pragma("unroll")                                           \
            for (int q = 0; q < 4; ++q) {                               \
                const int F = 16 * j + 4 * (S) + q;                     \
                const float val = vv[4 * j + q];                        \
                if (F % 3 == 0)      p0 = fmaf(comp[F / 3], val, p0);   \
                else if (F % 3 == 1) p1 = fmaf(comp[F / 3], val, p1);   \
                else                 p2 = fmaf(comp[F / 3], val, p2);   \
            }                                                           \
        }                                                               \
    }

__global__ __launch_bounds__(256)
void irradiance_kernel(const float* __restrict__ coeff,
                       const float* __restrict__ aabb,
                       const float* __restrict__ points,
                       const float* __restrict__ normals,
                       float* __restrict__ out,
                       int n)
{
    const int lane = threadIdx.x & 31;
    const long i = (long)blockIdx.x * (blockDim.x >> 5) + (threadIdx.x >> 5);
    if (i >= n) return;

    const int g = lane >> 2;   // corner 0..7
    const int s = lane & 3;    // sub-lane within corner group
    const int dxc = (g >> 2) & 1;
    const int dyc = (g >> 1) & 1;
    const int dzc = g & 1;

    // point & normal: all 32 lanes same address -> broadcast
    const float px = points[3 * i + 0];
    const float py = points[3 * i + 1];
    const float pz = points[3 * i + 2];
    const float nx = normals[3 * i + 0];
    const float ny = normals[3 * i + 1];
    const float nz = normals[3 * i + 2];

    const float amin0 = __ldg(&aabb[0]);
    const float amin1 = __ldg(&aabb[1]);
    const float amin2 = __ldg(&aabb[2]);
    const float amax0 = __ldg(&aabb[3]);
    const float amax1 = __ldg(&aabb[4]);
    const float amax2 = __ldg(&aabb[5]);

    const float RM1 = (float)(RES - 1);

    float gx = (px - amin0) / (amax0 - amin0) * RM1;
    float gy = (py - amin1) / (amax1 - amin1) * RM1;
    float gz = (pz - amin2) / (amax2 - amin2) * RM1;
    gx = fminf(fmaxf(gx, 0.0f), RM1);
    gy = fminf(fmaxf(gy, 0.0f), RM1);
    gz = fminf(fmaxf(gz, 0.0f), RM1);

    const int ix = min((int)floorf(gx), RES - 2);
    const int iy = min((int)floorf(gy), RES - 2);
    const int iz = min((int)floorf(gz), RES - 2);
    const float fx = gx - (float)ix;
    const float fy = gy - (float)iy;
    const float fz = gz - (float)iz;

    // corner weight
    const float w = (dxc ? fx : 1.0f - fx) * (dyc ? fy : 1.0f - fy) * (dzc ? fz : 1.0f - fz);

    // cooperative coalesced load of this corner's 192B cell:
    // instruction j -> group lanes read 64B contiguous (one 128B line)
    const long cell = (((long)(ix + dxc) * RES) + (iy + dyc)) * RES + (iz + dzc);
    const float4* b4 = (const float4*)(coeff + cell * COEFS_PER_CELL);
    float4 v0 = __ldcg(b4 + 0 + s);
    float4 v1 = __ldcg(b4 + 4 + s);
    float4 v2 = __ldcg(b4 + 8 + s);

    // SH components (degree 4), exact reference constants
    float comp[N_COMPS];
    {
        const float x = nx, y = ny, z = nz;
        const float xx = x * x, yy = y * y, zz = z * z;
        const float xy = x * y, yz = y * z, xz = x * z;
        comp[0]  =  0.28209479177387814f;
        comp[1]  = -0.4886025119029199f * y;
        comp[2]  =  0.4886025119029199f * z;
        comp[3]  = -0.4886025119029199f * x;
        comp[4]  =  1.0925484305920792f * xy;
        comp[5]  = -1.0925484305920792f * yz;
        comp[6]  =  0.31539156525252005f * (2.0f * zz - xx - yy);
        comp[7]  = -1.0925484305920792f * xz;
        comp[8]  =  0.5462742152960396f * (xx - yy);
        comp[9]  = -0.5900435899266435f * y * (3.0f * xx - yy);
        comp[10] =  2.890611442640554f  * xy * z;
        comp[11] = -0.4570457994644658f * y * (4.0f * zz - xx - yy);
        comp[12] =  0.3731763325901154f * z * (2.0f * zz - 3.0f * xx - 3.0f * yy);
        comp[13] = -0.4570457994644658f * x * (4.0f * zz - xx - yy);
        comp[14] =  1.445305721320277f  * z * (xx - yy);
        comp[15] = -0.5900435899266435f * x * (xx - 3.0f * yy);
    }

    float vv[12];
    *(float4*)&vv[0] = v0;
    *(float4*)&vv[4] = v1;
    *(float4*)&vv[8] = v2;

    float p0 = 0.0f, p1 = 0.0f, p2 = 0.0f;
    switch (s) {
        case 0: DOT4(0); break;
        case 1: DOT4(1); break;
        case 2: DOT4(2); break;
        default: DOT4(3); break;
    }

    float a0 = w * p0;
    float a1 = w * p1;
    float a2 = w * p2;

    // full-warp butterfly: every float of all 8 cells is held by exactly one lane
    #pragma unroll
    for (int off = 16; off > 0; off >>= 1) {
        a0 += __shfl_xor_sync(0xffffffffu, a0, off);
        a1 += __shfl_xor_sync(0xffffffffu, a1, off);
        a2 += __shfl_xor_sync(0xffffffffu, a2, off);
    }

    if (lane == 0) {
        out[3 * i + 0] = fmaxf(a0, 0.0f);
        out[3 * i + 1] = fmaxf(a1, 0.0f);
        out[3 * i + 2] = fmaxf(a2, 0.0f);
    }
}

extern "C" void kernel_launch(void* const* d_in, const int* in_sizes, int n_in,
                              void* d_out, int out_size)
{
    const float* coeff   = (const float*)d_in[0];
    const float* aabb    = (const float*)d_in[1];
    const float* points  = (const float*)d_in[2];
    const float* normals = (const float*)d_in[3];
    float* out = (float*)d_out;

    int n = in_sizes[2] / 3;          // 2,097,152 points
    int block = 256;                   // 8 warps = 8 points per block
    long warps = n;
    long grid = (warps * 32 + block - 1) / block;
    irradiance_kernel<<<(int)grid, block>>>(coeff, aabb, points, normals, out, n);
}

// round 4
// speedup vs baseline: 3.1449x; 1.3596x over previous
#include <cuda_runtime.h>

#define RES 128
#define NPTS_MAX 2097152   // 2^21 points; also 2^21 cell bins (128^3)

// ---------------- static scratch (no allocations allowed) ----------------
__device__ float  d_params[6];               // sx,sy,sz, ox,oy,oz
__device__ int    d_hist[NPTS_MAX];          // histogram -> per-1024-block exclusive offsets
__device__ int    d_btot[2048];              // per-scan-block totals
__device__ int    d_bsumx[2048];             // exclusive scan of block totals
__device__ int    d_cellid[NPTS_MAX];        // cell id per point
__device__ float4 d_pdata4[NPTS_MAX * 2];    // sorted payload: {px,py,pz,nx},{ny,nz,idx,0}

// ---------------- pass 0: transform params ----------------
__global__ void k_setup(const float* __restrict__ aabb)
{
    if (blockIdx.x == 0 && threadIdx.x == 0) {
        #pragma unroll
        for (int d = 0; d < 3; d++) {
            float amin = aabb[d], amax = aabb[d + 3];
            float s = 127.0f / (amax - amin);
            d_params[d]     = s;
            d_params[3 + d] = -amin * s;
        }
    }
}

// ---------------- pass 1: zero histogram ----------------
__global__ void k_zero()
{
    int i = blockIdx.x * blockDim.x + threadIdx.x;
    if (i < NPTS_MAX) d_hist[i] = 0;
}

// ---------------- pass 2: cell ids + histogram ----------------
__global__ void k_hist(const float* __restrict__ points, int n)
{
    int i = blockIdx.x * blockDim.x + threadIdx.x;
    if (i >= n) return;
    float sx = d_params[0], sy = d_params[1], sz = d_params[2];
    float ox = d_params[3], oy = d_params[4], oz = d_params[5];
    float gx = fminf(fmaxf(fmaf(points[3 * i + 0], sx, ox), 0.0f), 127.0f);
    float gy = fminf(fmaxf(fmaf(points[3 * i + 1], sy, oy), 0.0f), 127.0f);
    float gz = fminf(fmaxf(fmaf(points[3 * i + 2], sz, oz), 0.0f), 127.0f);
    int ix = min((int)gx, RES - 2);
    int iy = min((int)gy, RES - 2);
    int iz = min((int)gz, RES - 2);
    int cell = (ix << 14) | (iy << 7) | iz;
    d_cellid[i] = cell;
    atomicAdd(&d_hist[cell], 1);
}

// ---------------- pass 3: per-1024-chunk exclusive scan ----------------
__global__ void k_scan1()
{
    __shared__ int wsum[8];
    int tid = threadIdx.x;
    long base = (long)blockIdx.x * 1024 + tid * 4;
    int4 v = *(int4*)&d_hist[base];
    int t = v.x + v.y + v.z + v.w;
    int lane = tid & 31, wp = tid >> 5;
    int sc = t;
    #pragma unroll
    for (int off = 1; off < 32; off <<= 1) {
        int nv = __shfl_up_sync(0xffffffffu, sc, off);
        if (lane >= off) sc += nv;
    }
    if (lane == 31) wsum[wp] = sc;
    __syncthreads();
    if (tid < 8) {
        int ws = wsum[tid];
        #pragma unroll
        for (int off = 1; off < 8; off <<= 1) {
            int nv = __shfl_up_sync(0x000000ffu, ws, off);
            if (tid >= off) ws += nv;
        }
        wsum[tid] = ws;
    }
    __syncthreads();
    int excl = sc - t + (wp ? wsum[wp - 1] : 0);
    int4 o;
    o.x = excl; o.y = o.x + v.x; o.z = o.y + v.y; o.w = o.z + v.z;
    *(int4*)&d_hist[base] = o;
    if (tid == 255) d_btot[blockIdx.x] = excl + t;
}

// ---------------- pass 4: scan the 2048 block totals (1 block) ----------------
__global__ void k_scan2()
{
    __shared__ int wsum[8];
    int tid = threadIdx.x;
    int base = tid * 8;
    int v[8]; int t = 0;
    #pragma unroll
    for (int k = 0; k < 8; k++) { v[k] = d_btot[base + k]; t += v[k]; }
    int lane = tid & 31, wp = tid >> 5;
    int sc = t;
    #pragma unroll
    for (int off = 1; off < 32; off <<= 1) {
        int nv = __shfl_up_sync(0xffffffffu, sc, off);
        if (lane >= off) sc += nv;
    }
    if (lane == 31) wsum[wp] = sc;
    __syncthreads();
    if (tid < 8) {
        int ws = wsum[tid];
        #pragma unroll
        for (int off = 1; off < 8; off <<= 1) {
            int nv = __shfl_up_sync(0x000000ffu, ws, off);
            if (tid >= off) ws += nv;
        }
        wsum[tid] = ws;
    }
    __syncthreads();
    int run = sc - t + (wp ? wsum[wp - 1] : 0);
    #pragma unroll
    for (int k = 0; k < 8; k++) { d_bsumx[base + k] = run; run += v[k]; }
}

// ---------------- pass 5: scatter payloads into sorted order ----------------
__global__ void k_scatter(const float* __restrict__ points,
                          const float* __restrict__ normals, int n)
{
    int i = blockIdx.x * blockDim.x + threadIdx.x;
    if (i >= n) return;
    int cell = d_cellid[i];
    int pos = atomicAdd(&d_hist[cell], 1) + __ldg(&d_bsumx[cell >> 10]);
    float4 A, B;
    A.x = points[3 * i + 0]; A.y = points[3 * i + 1]; A.z = points[3 * i + 2];
    A.w = normals[3 * i + 0];
    B.x = normals[3 * i + 1]; B.y = normals[3 * i + 2];
    B.z = __int_as_float(i);  B.w = 0.0f;
    d_pdata4[(long)pos * 2 + 0] = A;
    d_pdata4[(long)pos * 2 + 1] = B;
}

// ---------------- pass 6: main kernel: 2 points/warp ----------------
// lane = 16*half + 4*grp + s ; corner per round rd: (dx=rd, dy=grp>>1, dz=grp&1)
#define DOT4(S)                                                         \
    {                                                                   \
        _Pragma("unroll")                                               \
        for (int j = 0; j < 3; ++j) {                                   \
            _Pragma("unroll")                                           \
            for (int q = 0; q < 4; ++q) {                               \
                const int F = 16 * j + 4 * (S) + q;                     \
                const float val = vv[4 * j + q];                        \
                if (F % 3 == 0)      p0 = fmaf(comp[F / 3], val, p0);   \
                else if (F % 3 == 1) p1 = fmaf(comp[F / 3], val, p1);   \
                else                 p2 = fmaf(comp[F / 3], val, p2);   \
            }                                                           \
        }                                                               \
    }

__global__ __launch_bounds__(256)
void k_main(const float* __restrict__ coeff, float* __restrict__ out, int n)
{
    const int lane = threadIdx.x & 31;
    const long wid = ((long)blockIdx.x * blockDim.x + threadIdx.x) >> 5;
    const int half = lane >> 4;
    const int r    = lane & 15;
    const int grp  = r >> 2;
    const int s    = r & 3;

    long pi = wid * 2 + half;
    if (pi >= n) pi = n - 1;           // whole warp stays active for shuffles

    const float4 A = d_pdata4[pi * 2 + 0];
    const float4 B = d_pdata4[pi * 2 + 1];
    const float px = A.x, py = A.y, pz = A.z;
    const float nx = A.w, ny = B.x, nz = B.y;
    const int oidx = __float_as_int(B.z);

    const float sx = d_params[0], sy = d_params[1], sz = d_params[2];
    const float ox = d_params[3], oy = d_params[4], oz = d_params[5];

    float gx = fminf(fmaxf(fmaf(px, sx, ox), 0.0f), 127.0f);
    float gy = fminf(fmaxf(fmaf(py, sy, oy), 0.0f), 127.0f);
    float gz = fminf(fmaxf(fmaf(pz, sz, oz), 0.0f), 127.0f);
    const int ix = min((int)gx, RES - 2);
    const int iy = min((int)gy, RES - 2);
    const int iz = min((int)gz, RES - 2);
    const float fx = gx - (float)ix;
    const float fy = gy - (float)iy;
    const float fz = gz - (float)iz;

    // SH components (degree 4), exact reference constants
    float comp[16];
    {
        const float x = nx, y = ny, z = nz;
        const float xx = x * x, yy = y * y, zz = z * z;
        const float xy = x * y, yz = y * z, xz = x * z;
        comp[0]  =  0.28209479177387814f;
        comp[1]  = -0.4886025119029199f * y;
        comp[2]  =  0.4886025119029199f * z;
        comp[3]  = -0.4886025119029199f * x;
        comp[4]  =  1.0925484305920792f * xy;
        comp[5]  = -1.0925484305920792f * yz;
        comp[6]  =  0.31539156525252005f * (2.0f * zz - xx - yy);
        comp[7]  = -1.0925484305920792f * xz;
        comp[8]  =  0.5462742152960396f * (xx - yy);
        comp[9]  = -0.5900435899266435f * y * (3.0f * xx - yy);
        comp[10] =  2.890611442640554f  * xy * z;
        comp[11] = -0.4570457994644658f * y * (4.0f * zz - xx - yy);
        comp[12] =  0.3731763325901154f * z * (2.0f * zz - 3.0f * xx - 3.0f * yy);
        comp[13] = -0.4570457994644658f * x * (4.0f * zz - xx - yy);
        comp[14] =  1.445305721320277f  * z * (xx - yy);
        comp[15] = -0.5900435899266435f * x * (xx - 3.0f * yy);
    }

    const int dyc = (grp >> 1) & 1;
    const int dzc = grp & 1;
    const float wyz = (dyc ? fy : 1.0f - fy) * (dzc ? fz : 1.0f - fz);

    float a0 = 0.0f, a1 = 0.0f, a2 = 0.0f;

    #pragma unroll
    for (int rd = 0; rd < 2; rd++) {
        const long cell = (((long)(ix + rd) * RES) + (iy + dyc)) * RES + (iz + dzc);
        const float4* b4 = (const float4*)(coeff + cell * 48);
        float4 v0 = __ldg(b4 + 0 + s);
        float4 v1 = __ldg(b4 + 4 + s);
        float4 v2 = __ldg(b4 + 8 + s);
        float vv[12];
        *(float4*)&vv[0] = v0;
        *(float4*)&vv[4] = v1;
        *(float4*)&vv[8] = v2;

        float p0 = 0.0f, p1 = 0.0f, p2 = 0.0f;
        switch (s) {
            case 0: DOT4(0); break;
            case 1: DOT4(1); break;
            case 2: DOT4(2); break;
            default: DOT4(3); break;
        }
        const float w = (rd ? fx : 1.0f - fx) * wyz;
        a0 = fmaf(w, p0, a0);
        a1 = fmaf(w, p1, a1);
        a2 = fmaf(w, p2, a2);
    }

    // quad reduce all 3 channels
    a0 += __shfl_xor_sync(0xffffffffu, a0, 1);
    a0 += __shfl_xor_sync(0xffffffffu, a0, 2);
    a1 += __shfl_xor_sync(0xffffffffu, a1, 1);
    a1 += __shfl_xor_sync(0xffffffffu, a1, 2);
    a2 += __shfl_xor_sync(0xffffffffu, a2, 1);
    a2 += __shfl_xor_sync(0xffffffffu, a2, 2);
    // channel-to-lane, then reduce across the 4 groups of this half
    float v = (s == 0) ? a0 : (s == 1) ? a1 : a2;
    v += __shfl_xor_sync(0xffffffffu, v, 4);
    v += __shfl_xor_sync(0xffffffffu, v, 8);

    if (s < 3) out[3 * (long)oidx + s] = fmaxf(v, 0.0f);
}

// ---------------- launcher ----------------
extern "C" void kernel_launch(void* const* d_in, const int* in_sizes, int n_in,
                              void* d_out, int out_size)
{
    const float* coeff   = (const float*)d_in[0];
    const float* aabb    = (const float*)d_in[1];
    const float* points  = (const float*)d_in[2];
    const float* normals = (const float*)d_in[3];
    float* out = (float*)d_out;

    int n = in_sizes[2] / 3;

    k_setup<<<1, 32>>>(aabb);
    k_zero<<<NPTS_MAX / 256, 256>>>();
    k_hist<<<(n + 255) / 256, 256>>>(points, n);
    k_scan1<<<2048, 256>>>();
    k_scan2<<<1, 256>>>();
    k_scatter<<<(n + 255) / 256, 256>>>(points, normals, n);

    long warps = (n + 1) / 2;                  // 2 points per warp
    long threads = warps * 32;
    int block = 256;
    long grid = (threads + block - 1) / block;
    k_main<<<(int)grid, block>>>(coeff, out, n);
}

// round 5
// speedup vs baseline: 3.5821x; 1.1390x over previous
#include <cuda_runtime.h>

#define RES 128
#define NPTS_MAX 2097152

// ---------------- static scratch ----------------
__device__ float  d_params[6];
__device__ int    d_hist[NPTS_MAX];
__device__ int    d_btot[2048];
__device__ int    d_bsumx[2048];
__device__ int    d_cellid[NPTS_MAX];
__device__ float4 d_pdata4[NPTS_MAX * 2];   // sorted: {gx,gy,gz,nx},{ny,nz,idx,0}

__global__ void k_setup(const float* __restrict__ aabb)
{
    if (blockIdx.x == 0 && threadIdx.x == 0) {
        #pragma unroll
        for (int d = 0; d < 3; d++) {
            float amin = aabb[d], amax = aabb[d + 3];
            float s = 127.0f / (amax - amin);
            d_params[d]     = s;
            d_params[3 + d] = -amin * s;
        }
    }
}

__global__ void k_zero()
{
    int i = blockIdx.x * blockDim.x + threadIdx.x;
    if (i < NPTS_MAX) d_hist[i] = 0;
}

__global__ void k_hist(const float* __restrict__ points, int n)
{
    int i = blockIdx.x * blockDim.x + threadIdx.x;
    if (i >= n) return;
    float sx = d_params[0], sy = d_params[1], sz = d_params[2];
    float ox = d_params[3], oy = d_params[4], oz = d_params[5];
    float gx = fminf(fmaxf(fmaf(points[3 * i + 0], sx, ox), 0.0f), 127.0f);
    float gy = fminf(fmaxf(fmaf(points[3 * i + 1], sy, oy), 0.0f), 127.0f);
    float gz = fminf(fmaxf(fmaf(points[3 * i + 2], sz, oz), 0.0f), 127.0f);
    int ix = min((int)gx, RES - 2);
    int iy = min((int)gy, RES - 2);
    int iz = min((int)gz, RES - 2);
    int cell = (ix << 14) | (iy << 7) | iz;
    d_cellid[i] = cell;
    atomicAdd(&d_hist[cell], 1);
}

__global__ void k_scan1()
{
    __shared__ int wsum[8];
    int tid = threadIdx.x;
    long base = (long)blockIdx.x * 1024 + tid * 4;
    int4 v = *(int4*)&d_hist[base];
    int t = v.x + v.y + v.z + v.w;
    int lane = tid & 31, wp = tid >> 5;
    int sc = t;
    #pragma unroll
    for (int off = 1; off < 32; off <<= 1) {
        int nv = __shfl_up_sync(0xffffffffu, sc, off);
        if (lane >= off) sc += nv;
    }
    if (lane == 31) wsum[wp] = sc;
    __syncthreads();
    if (tid < 8) {
        int ws = wsum[tid];
        #pragma unroll
        for (int off = 1; off < 8; off <<= 1) {
            int nv = __shfl_up_sync(0x000000ffu, ws, off);
            if (tid >= off) ws += nv;
        }
        wsum[tid] = ws;
    }
    __syncthreads();
    int excl = sc - t + (wp ? wsum[wp - 1] : 0);
    int4 o;
    o.x = excl; o.y = o.x + v.x; o.z = o.y + v.y; o.w = o.z + v.z;
    *(int4*)&d_hist[base] = o;
    if (tid == 255) d_btot[blockIdx.x] = excl + t;
}

__global__ void k_scan2()
{
    __shared__ int wsum[8];
    int tid = threadIdx.x;
    int base = tid * 8;
    int v[8]; int t = 0;
    #pragma unroll
    for (int k = 0; k < 8; k++) { v[k] = d_btot[base + k]; t += v[k]; }
    int lane = tid & 31, wp = tid >> 5;
    int sc = t;
    #pragma unroll
    for (int off = 1; off < 32; off <<= 1) {
        int nv = __shfl_up_sync(0xffffffffu, sc, off);
        if (lane >= off) sc += nv;
    }
    if (lane == 31) wsum[wp] = sc;
    __syncthreads();
    if (tid < 8) {
        int ws = wsum[tid];
        #pragma unroll
        for (int off = 1; off < 8; off <<= 1) {
            int nv = __shfl_up_sync(0x000000ffu, ws, off);
            if (tid >= off) ws += nv;
        }
        wsum[tid] = ws;
    }
    __syncthreads();
    int run = sc - t + (wp ? wsum[wp - 1] : 0);
    #pragma unroll
    for (int k = 0; k < 8; k++) { d_bsumx[base + k] = run; run += v[k]; }
}

__global__ void k_scatter(const float* __restrict__ points,
                          const float* __restrict__ normals, int n)
{
    int i = blockIdx.x * blockDim.x + threadIdx.x;
    if (i >= n) return;
    int cell = d_cellid[i];
    int pos = atomicAdd(&d_hist[cell], 1) + __ldg(&d_bsumx[cell >> 10]);
    float sx = d_params[0], sy = d_params[1], sz = d_params[2];
    float ox = d_params[3], oy = d_params[4], oz = d_params[5];
    float4 A, B;
    A.x = fminf(fmaxf(fmaf(points[3 * i + 0], sx, ox), 0.0f), 127.0f);
    A.y = fminf(fmaxf(fmaf(points[3 * i + 1], sy, oy), 0.0f), 127.0f);
    A.z = fminf(fmaxf(fmaf(points[3 * i + 2], sz, oz), 0.0f), 127.0f);
    A.w = normals[3 * i + 0];
    B.x = normals[3 * i + 1]; B.y = normals[3 * i + 2];
    B.z = __int_as_float(i);  B.w = 0.0f;
    d_pdata4[(long)pos * 2 + 0] = A;
    d_pdata4[(long)pos * 2 + 1] = B;
}

// ---------------- main: 4 points/warp ----------------
// lane = 8*p + 4*g + s ; p = point-in-warp, g = dz, s = float4 sub-lane.
// rounds rd=0..3: dx = rd>>1, dy = rd&1.
#define DOT4(S)                                                         \
    {                                                                   \
        _Pragma("unroll")                                               \
        for (int j = 0; j < 3; ++j) {                                   \
            _Pragma("unroll")                                           \
            for (int q = 0; q < 4; ++q) {                               \
                const int F = 16 * j + 4 * (S) + q;                     \
                const float val = vv[4 * j + q];                        \
                if (F % 3 == 0)      p0 = fmaf(comp[F / 3], val, p0);   \
                else if (F % 3 == 1) p1 = fmaf(comp[F / 3], val, p1);   \
                else                 p2 = fmaf(comp[F / 3], val, p2);   \
            }                                                           \
        }                                                               \
    }

__global__ __launch_bounds__(256)
void k_main(const float* __restrict__ coeff, float* __restrict__ out, int n)
{
    const int lane = threadIdx.x & 31;
    const long wid = ((long)blockIdx.x * blockDim.x + threadIdx.x) >> 5;
    const int p = lane >> 3;        // point in warp 0..3
    const int g = (lane >> 2) & 1;  // dz
    const int s = lane & 3;

    long pi = wid * 4 + p;
    if (pi >= n) pi = n - 1;

    const float4 A = d_pdata4[pi * 2 + 0];
    const float4 B = d_pdata4[pi * 2 + 1];
    const float gx = A.x, gy = A.y, gz = A.z;
    const float nx = A.w, ny = B.x, nz = B.y;
    const int oidx = __float_as_int(B.z);

    const int ix = min((int)gx, RES - 2);
    const int iy = min((int)gy, RES - 2);
    const int iz = min((int)gz, RES - 2);
    const float fx = gx - (float)ix;
    const float fy = gy - (float)iy;
    const float fz = gz - (float)iz;

    float comp[16];
    {
        const float x = nx, y = ny, z = nz;
        const float xx = x * x, yy = y * y, zz = z * z;
        const float xy = x * y, yz = y * z, xz = x * z;
        comp[0]  =  0.28209479177387814f;
        comp[1]  = -0.4886025119029199f * y;
        comp[2]  =  0.4886025119029199f * z;
        comp[3]  = -0.4886025119029199f * x;
        comp[4]  =  1.0925484305920792f * xy;
        comp[5]  = -1.0925484305920792f * yz;
        comp[6]  =  0.31539156525252005f * (2.0f * zz - xx - yy);
        comp[7]  = -1.0925484305920792f * xz;
        comp[8]  =  0.5462742152960396f * (xx - yy);
        comp[9]  = -0.5900435899266435f * y * (3.0f * xx - yy);
        comp[10] =  2.890611442640554f  * xy * z;
        comp[11] = -0.4570457994644658f * y * (4.0f * zz - xx - yy);
        comp[12] =  0.3731763325901154f * z * (2.0f * zz - 3.0f * xx - 3.0f * yy);
        comp[13] = -0.4570457994644658f * x * (4.0f * zz - xx - yy);
        comp[14] =  1.445305721320277f  * z * (xx - yy);
        comp[15] = -0.5900435899266435f * x * (xx - 3.0f * yy);
    }

    const float wz = g ? fz : 1.0f - fz;
    const float wx0 = 1.0f - fx, wy0 = 1.0f - fy;

    float a0 = 0.0f, a1 = 0.0f, a2 = 0.0f;

    #pragma unroll
    for (int rd = 0; rd < 4; rd++) {
        const int dx = rd >> 1, dy = rd & 1;
        const long cell = (((long)(ix + dx) * RES) + (iy + dy)) * RES + (iz + g);
        const float4* b4 = (const float4*)(coeff + cell * 48);
        float4 v0 = __ldg(b4 + 0 + s);
        float4 v1 = __ldg(b4 + 4 + s);
        float4 v2 = __ldg(b4 + 8 + s);
        float vv[12];
        *(float4*)&vv[0] = v0;
        *(float4*)&vv[4] = v1;
        *(float4*)&vv[8] = v2;

        float p0 = 0.0f, p1 = 0.0f, p2 = 0.0f;
        switch (s) {
            case 0: DOT4(0); break;
            case 1: DOT4(1); break;
            case 2: DOT4(2); break;
            default: DOT4(3); break;
        }
        const float w = (dx ? fx : wx0) * (dy ? fy : wy0) * wz;
        a0 = fmaf(w, p0, a0);
        a1 = fmaf(w, p1, a1);
        a2 = fmaf(w, p2, a2);
    }

    // reduce over s (xor 1,2) then over g (xor 4); stays within the 8 lanes of a point
    a0 += __shfl_xor_sync(0xffffffffu, a0, 1);
    a0 += __shfl_xor_sync(0xffffffffu, a0, 2);
    a0 += __shfl_xor_sync(0xffffffffu, a0, 4);
    a1 += __shfl_xor_sync(0xffffffffu, a1, 1);
    a1 += __shfl_xor_sync(0xffffffffu, a1, 2);
    a1 += __shfl_xor_sync(0xffffffffu, a1, 4);
    a2 += __shfl_xor_sync(0xffffffffu, a2, 1);
    a2 += __shfl_xor_sync(0xffffffffu, a2, 2);
    a2 += __shfl_xor_sync(0xffffffffu, a2, 4);

    if (g == 0 && s < 3) {
        float v = (s == 0) ? a0 : (s == 1) ? a1 : a2;
        out[3 * (long)oidx + s] = fmaxf(v, 0.0f);
    }
}

extern "C" void kernel_launch(void* const* d_in, const int* in_sizes, int n_in,
                              void* d_out, int out_size)
{
    const float* coeff   = (const float*)d_in[0];
    const float* aabb    = (const float*)d_in[1];
    const float* points  = (const float*)d_in[2];
    const float* normals = (const float*)d_in[3];
    float* out = (float*)d_out;

    int n = in_sizes[2] / 3;

    k_setup<<<1, 32>>>(aabb);
    k_zero<<<NPTS_MAX / 256, 256>>>();
    k_hist<<<(n + 255) / 256, 256>>>(points, n);
    k_scan1<<<2048, 256>>>();
    k_scan2<<<1, 256>>>();
    k_scatter<<<(n + 255) / 256, 256>>>(points, normals, n);

    long warps = (n + 3) / 4;                 // 4 points per warp
    long threads = warps * 32;
    int block = 256;
    long grid = (threads + block - 1) / block;
    k_main<<<(int)grid, block>>>(coeff, out, n);
}

// round 6
// speedup vs baseline: 4.3367x; 1.2107x over previous
#include <cuda_runtime.h>

#define RES 128
#define NPTS_MAX 2097152

// ---------------- static scratch ----------------
__device__ float  d_params[6];
__device__ int    d_hist[NPTS_MAX];
__device__ int    d_btot[2048];
__device__ int    d_bsumx[2048];
__device__ int    d_cellid[NPTS_MAX];
__device__ float4 d_pdata4[NPTS_MAX * 2];   // sorted: {gx,gy,gz,nx},{ny,nz,idx,0}

__global__ void k_setup(const float* __restrict__ aabb)
{
    if (blockIdx.x == 0 && threadIdx.x == 0) {
        #pragma unroll
        for (int d = 0; d < 3; d++) {
            float amin = aabb[d], amax = aabb[d + 3];
            float s = 127.0f / (amax - amin);
            d_params[d]     = s;
            d_params[3 + d] = -amin * s;
        }
    }
}

__global__ void k_zero()
{
    int i = blockIdx.x * blockDim.x + threadIdx.x;
    if (i < NPTS_MAX) d_hist[i] = 0;
}

__global__ void k_hist(const float* __restrict__ points, int n)
{
    int i = blockIdx.x * blockDim.x + threadIdx.x;
    if (i >= n) return;
    float sx = d_params[0], sy = d_params[1], sz = d_params[2];
    float ox = d_params[3], oy = d_params[4], oz = d_params[5];
    float gx = fminf(fmaxf(fmaf(points[3 * i + 0], sx, ox), 0.0f), 127.0f);
    float gy = fminf(fmaxf(fmaf(points[3 * i + 1], sy, oy), 0.0f), 127.0f);
    float gz = fminf(fmaxf(fmaf(points[3 * i + 2], sz, oz), 0.0f), 127.0f);
    int ix = min((int)gx, RES - 2);
    int iy = min((int)gy, RES - 2);
    int iz = min((int)gz, RES - 2);
    int cell = (ix << 14) | (iy << 7) | iz;
    d_cellid[i] = cell;
    atomicAdd(&d_hist[cell], 1);
}

__global__ void k_scan1()
{
    __shared__ int wsum[8];
    int tid = threadIdx.x;
    long base = (long)blockIdx.x * 1024 + tid * 4;
    int4 v = *(int4*)&d_hist[base];
    int t = v.x + v.y + v.z + v.w;
    int lane = tid & 31, wp = tid >> 5;
    int sc = t;
    #pragma unroll
    for (int off = 1; off < 32; off <<= 1) {
        int nv = __shfl_up_sync(0xffffffffu, sc, off);
        if (lane >= off) sc += nv;
    }
    if (lane == 31) wsum[wp] = sc;
    __syncthreads();
    if (tid < 8) {
        int ws = wsum[tid];
        #pragma unroll
        for (int off = 1; off < 8; off <<= 1) {
            int nv = __shfl_up_sync(0x000000ffu, ws, off);
            if (tid >= off) ws += nv;
        }
        wsum[tid] = ws;
    }
    __syncthreads();
    int excl = sc - t + (wp ? wsum[wp - 1] : 0);
    int4 o;
    o.x = excl; o.y = o.x + v.x; o.z = o.y + v.y; o.w = o.z + v.z;
    *(int4*)&d_hist[base] = o;
    if (tid == 255) d_btot[blockIdx.x] = excl + t;
}

__global__ void k_scan2()
{
    __shared__ int wsum[8];
    int tid = threadIdx.x;
    int base = tid * 8;
    int v[8]; int t = 0;
    #pragma unroll
    for (int k = 0; k < 8; k++) { v[k] = d_btot[base + k]; t += v[k]; }
    int lane = tid & 31, wp = tid >> 5;
    int sc = t;
    #pragma unroll
    for (int off = 1; off < 32; off <<= 1) {
        int nv = __shfl_up_sync(0xffffffffu, sc, off);
        if (lane >= off) sc += nv;
    }
    if (lane == 31) wsum[wp] = sc;
    __syncthreads();
    if (tid < 8) {
        int ws = wsum[tid];
        #pragma unroll
        for (int off = 1; off < 8; off <<= 1) {
            int nv = __shfl_up_sync(0x000000ffu, ws, off);
            if (tid >= off) ws += nv;
        }
        wsum[tid] = ws;
    }
    __syncthreads();
    int run = sc - t + (wp ? wsum[wp - 1] : 0);
    #pragma unroll
    for (int k = 0; k < 8; k++) { d_bsumx[base + k] = run; run += v[k]; }
}

__global__ void k_scatter(const float* __restrict__ points,
                          const float* __restrict__ normals, int n)
{
    int i = blockIdx.x * blockDim.x + threadIdx.x;
    if (i >= n) return;
    int cell = d_cellid[i];
    int pos = atomicAdd(&d_hist[cell], 1) + __ldg(&d_bsumx[cell >> 10]);
    float sx = d_params[0], sy = d_params[1], sz = d_params[2];
    float ox = d_params[3], oy = d_params[4], oz = d_params[5];
    float4 A, B;
    A.x = fminf(fmaxf(fmaf(points[3 * i + 0], sx, ox), 0.0f), 127.0f);
    A.y = fminf(fmaxf(fmaf(points[3 * i + 1], sy, oy), 0.0f), 127.0f);
    A.z = fminf(fmaxf(fmaf(points[3 * i + 2], sz, oz), 0.0f), 127.0f);
    A.w = normals[3 * i + 0];
    B.x = normals[3 * i + 1]; B.y = normals[3 * i + 2];
    B.z = __int_as_float(i);  B.w = 0.0f;
    d_pdata4[(long)pos * 2 + 0] = A;
    d_pdata4[(long)pos * 2 + 1] = B;
}

// ---------------- main: 4 points/warp, trilerp-first then one dot ----------------
// lane = 8*p + 4*g + s ; p = point-in-warp, g = dz, s = float4 sub-lane.
#define DOT4(S)                                                          \
    {                                                                    \
        _Pragma("unroll")                                                \
        for (int j = 0; j < 3; ++j) {                                    \
            _Pragma("unroll")                                            \
            for (int q = 0; q < 4; ++q) {                                \
                const int F = 16 * j + 4 * (S) + q;                      \
                const float val = wv[4 * j + q];                         \
                if (F % 3 == 0)      p0 = fmaf(comp[F / 3], val, p0);    \
                else if (F % 3 == 1) p1 = fmaf(comp[F / 3], val, p1);    \
                else                 p2 = fmaf(comp[F / 3], val, p2);    \
            }                                                            \
        }                                                                \
    }

__global__ __launch_bounds__(256)
void k_main(const float* __restrict__ coeff, float* __restrict__ out, int n)
{
    const int lane = threadIdx.x & 31;
    const long wid = ((long)blockIdx.x * blockDim.x + threadIdx.x) >> 5;
    const int p = lane >> 3;
    const int g = (lane >> 2) & 1;
    const int s = lane & 3;

    long pi = wid * 4 + p;
    if (pi >= n) pi = n - 1;

    const float4 A = d_pdata4[pi * 2 + 0];
    const float4 B = d_pdata4[pi * 2 + 1];
    const float gx = A.x, gy = A.y, gz = A.z;
    const float nx = A.w, ny = B.x, nz = B.y;
    const int oidx = __float_as_int(B.z);

    const int ix = min((int)gx, RES - 2);
    const int iy = min((int)gy, RES - 2);
    const int iz = min((int)gz, RES - 2);
    const float fx = gx - (float)ix;
    const float fy = gy - (float)iy;
    const float fz = gz - (float)iz;

    const float wz  = g ? fz : 1.0f - fz;
    const float wx0 = 1.0f - fx, wy0 = 1.0f - fy;

    // base pointer for corner (0,0,g), sub-lane s; round offsets are constants
    const long cell0 = (((long)ix * RES) + iy) * RES + (iz + g);
    const float4* b4 = (const float4*)(coeff + cell0 * 48) + s;

    float wv[12];
    #pragma unroll
    for (int k = 0; k < 12; k++) wv[k] = 0.0f;

    #pragma unroll
    for (int rd = 0; rd < 4; rd++) {
        const int dx = rd >> 1, dy = rd & 1;
        const float4* c4 = b4 + (dx * (RES * RES * 12) + dy * (RES * 12));
        float4 v0 = __ldg(c4 + 0);
        float4 v1 = __ldg(c4 + 4);
        float4 v2 = __ldg(c4 + 8);
        const float w = (dx ? fx : wx0) * (dy ? fy : wy0) * wz;
        wv[0] = fmaf(w, v0.x, wv[0]);  wv[1]  = fmaf(w, v0.y, wv[1]);
        wv[2] = fmaf(w, v0.z, wv[2]);  wv[3]  = fmaf(w, v0.w, wv[3]);
        wv[4] = fmaf(w, v1.x, wv[4]);  wv[5]  = fmaf(w, v1.y, wv[5]);
        wv[6] = fmaf(w, v1.z, wv[6]);  wv[7]  = fmaf(w, v1.w, wv[7]);
        wv[8] = fmaf(w, v2.x, wv[8]);  wv[9]  = fmaf(w, v2.y, wv[9]);
        wv[10] = fmaf(w, v2.z, wv[10]); wv[11] = fmaf(w, v2.w, wv[11]);
    }

    // SH components (degree 4), exact reference constants
    float comp[16];
    {
        const float x = nx, y = ny, z = nz;
        const float xx = x * x, yy = y * y, zz = z * z;
        const float xy = x * y, yz = y * z, xz = x * z;
        comp[0]  =  0.28209479177387814f;
        comp[1]  = -0.4886025119029199f * y;
        comp[2]  =  0.4886025119029199f * z;
        comp[3]  = -0.4886025119029199f * x;
        comp[4]  =  1.0925484305920792f * xy;
        comp[5]  = -1.0925484305920792f * yz;
        comp[6]  =  0.31539156525252005f * (2.0f * zz - xx - yy);
        comp[7]  = -1.0925484305920792f * xz;
        comp[8]  =  0.5462742152960396f * (xx - yy);
        comp[9]  = -0.5900435899266435f * y * (3.0f * xx - yy);
        comp[10] =  2.890611442640554f  * xy * z;
        comp[11] = -0.4570457994644658f * y * (4.0f * zz - xx - yy);
        comp[12] =  0.3731763325901154f * z * (2.0f * zz - 3.0f * xx - 3.0f * yy);
        comp[13] = -0.4570457994644658f * x * (4.0f * zz - xx - yy);
        comp[14] =  1.445305721320277f  * z * (xx - yy);
        comp[15] = -0.5900435899266435f * x * (xx - 3.0f * yy);
    }

    float p0 = 0.0f, p1 = 0.0f, p2 = 0.0f;
    switch (s) {
        case 0: DOT4(0); break;
        case 1: DOT4(1); break;
        case 2: DOT4(2); break;
        default: DOT4(3); break;
    }

    // reduce over s (xor 1,2) then g (xor 4)
    p0 += __shfl_xor_sync(0xffffffffu, p0, 1);
    p0 += __shfl_xor_sync(0xffffffffu, p0, 2);
    p0 += __shfl_xor_sync(0xffffffffu, p0, 4);
    p1 += __shfl_xor_sync(0xffffffffu, p1, 1);
    p1 += __shfl_xor_sync(0xffffffffu, p1, 2);
    p1 += __shfl_xor_sync(0xffffffffu, p1, 4);
    p2 += __shfl_xor_sync(0xffffffffu, p2, 1);
    p2 += __shfl_xor_sync(0xffffffffu, p2, 2);
    p2 += __shfl_xor_sync(0xffffffffu, p2, 4);

    if (g == 0 && s < 3) {
        float v = (s == 0) ? p0 : (s == 1) ? p1 : p2;
        out[3 * (long)oidx + s] = fmaxf(v, 0.0f);
    }
}

extern "C" void kernel_launch(void* const* d_in, const int* in_sizes, int n_in,
                              void* d_out, int out_size)
{
    const float* coeff   = (const float*)d_in[0];
    const float* aabb    = (const float*)d_in[1];
    const float* points  = (const float*)d_in[2];
    const float* normals = (const float*)d_in[3];
    float* out = (float*)d_out;

    int n = in_sizes[2] / 3;

    k_setup<<<1, 32>>>(aabb);
    k_zero<<<NPTS_MAX / 256, 256>>>();
    k_hist<<<(n + 255) / 256, 256>>>(points, n);
    k_scan1<<<2048, 256>>>();
    k_scan2<<<1, 256>>>();
    k_scatter<<<(n + 255) / 256, 256>>>(points, normals, n);

    long warps = (n + 3) / 4;
    long threads = warps * 32;
    int block = 256;
    long grid = (threads + block - 1) / block;
    k_main<<<(int)grid, block>>>(coeff, out, n);
}

// round 7
// speedup vs baseline: 4.6853x; 1.0804x over previous
#include <cuda_runtime.h>

#define RES 128
#define NPTS_MAX 2097152

// ---------------- static scratch ----------------
__device__ float  d_params[6];
__device__ int    d_hist[NPTS_MAX];
__device__ int    d_btot[2048];
__device__ int    d_bsumx[2048];
__device__ int    d_cellid[NPTS_MAX];
__device__ float4 d_pdata4[NPTS_MAX * 2];   // sorted: {gx,gy,gz,nx},{ny,nz,idx,0}

__global__ void k_setup(const float* __restrict__ aabb)
{
    if (blockIdx.x == 0 && threadIdx.x == 0) {
        #pragma unroll
        for (int d = 0; d < 3; d++) {
            float amin = aabb[d], amax = aabb[d + 3];
            float s = 127.0f / (amax - amin);
            d_params[d]     = s;
            d_params[3 + d] = -amin * s;
        }
    }
}

__global__ void k_zero()
{
    int i = blockIdx.x * blockDim.x + threadIdx.x;
    if (i < NPTS_MAX) d_hist[i] = 0;
}

__global__ void k_hist(const float* __restrict__ points, int n)
{
    int i = blockIdx.x * blockDim.x + threadIdx.x;
    if (i >= n) return;
    float sx = d_params[0], sy = d_params[1], sz = d_params[2];
    float ox = d_params[3], oy = d_params[4], oz = d_params[5];
    float gx = fminf(fmaxf(fmaf(points[3 * i + 0], sx, ox), 0.0f), 127.0f);
    float gy = fminf(fmaxf(fmaf(points[3 * i + 1], sy, oy), 0.0f), 127.0f);
    float gz = fminf(fmaxf(fmaf(points[3 * i + 2], sz, oz), 0.0f), 127.0f);
    int ix = min((int)gx, RES - 2);
    int iy = min((int)gy, RES - 2);
    int iz = min((int)gz, RES - 2);
    int cell = (ix << 14) | (iy << 7) | iz;
    d_cellid[i] = cell;
    atomicAdd(&d_hist[cell], 1);
}

__global__ void k_scan1()
{
    __shared__ int wsum[8];
    int tid = threadIdx.x;
    long base = (long)blockIdx.x * 1024 + tid * 4;
    int4 v = *(int4*)&d_hist[base];
    int t = v.x + v.y + v.z + v.w;
    int lane = tid & 31, wp = tid >> 5;
    int sc = t;
    #pragma unroll
    for (int off = 1; off < 32; off <<= 1) {
        int nv = __shfl_up_sync(0xffffffffu, sc, off);
        if (lane >= off) sc += nv;
    }
    if (lane == 31) wsum[wp] = sc;
    __syncthreads();
    if (tid < 8) {
        int ws = wsum[tid];
        #pragma unroll
        for (int off = 1; off < 8; off <<= 1) {
            int nv = __shfl_up_sync(0x000000ffu, ws, off);
            if (tid >= off) ws += nv;
        }
        wsum[tid] = ws;
    }
    __syncthreads();
    int excl = sc - t + (wp ? wsum[wp - 1] : 0);
    int4 o;
    o.x = excl; o.y = o.x + v.x; o.z = o.y + v.y; o.w = o.z + v.z;
    *(int4*)&d_hist[base] = o;
    if (tid == 255) d_btot[blockIdx.x] = excl + t;
}

__global__ void k_scan2()
{
    __shared__ int wsum[8];
    int tid = threadIdx.x;
    int base = tid * 8;
    int v[8]; int t = 0;
    #pragma unroll
    for (int k = 0; k < 8; k++) { v[k] = d_btot[base + k]; t += v[k]; }
    int lane = tid & 31, wp = tid >> 5;
    int sc = t;
    #pragma unroll
    for (int off = 1; off < 32; off <<= 1) {
        int nv = __shfl_up_sync(0xffffffffu, sc, off);
        if (lane >= off) sc += nv;
    }
    if (lane == 31) wsum[wp] = sc;
    __syncthreads();
    if (tid < 8) {
        int ws = wsum[tid];
        #pragma unroll
        for (int off = 1; off < 8; off <<= 1) {
            int nv = __shfl_up_sync(0x000000ffu, ws, off);
            if (tid >= off) ws += nv;
        }
        wsum[tid] = ws;
    }
    __syncthreads();
    int run = sc - t + (wp ? wsum[wp - 1] : 0);
    #pragma unroll
    for (int k = 0; k < 8; k++) { d_bsumx[base + k] = run; run += v[k]; }
}

__global__ void k_scatter(const float* __restrict__ points,
                          const float* __restrict__ normals, int n)
{
    int i = blockIdx.x * blockDim.x + threadIdx.x;
    if (i >= n) return;
    int cell = d_cellid[i];
    int pos = atomicAdd(&d_hist[cell], 1) + __ldg(&d_bsumx[cell >> 10]);
    float sx = d_params[0], sy = d_params[1], sz = d_params[2];
    float ox = d_params[3], oy = d_params[4], oz = d_params[5];
    float4 A, B;
    A.x = fminf(fmaxf(fmaf(points[3 * i + 0], sx, ox), 0.0f), 127.0f);
    A.y = fminf(fmaxf(fmaf(points[3 * i + 1], sy, oy), 0.0f), 127.0f);
    A.z = fminf(fmaxf(fmaf(points[3 * i + 2], sz, oz), 0.0f), 127.0f);
    A.w = normals[3 * i + 0];
    B.x = normals[3 * i + 1]; B.y = normals[3 * i + 2];
    B.z = __int_as_float(i);  B.w = 0.0f;
    d_pdata4[(long)pos * 2 + 0] = A;
    d_pdata4[(long)pos * 2 + 1] = B;
}

// ---------------- main: 8 points/warp, uniform dot ----------------
// lane = 4*p + s. Lane s owns cell floats F = 12s + m (m=0..11):
//   float4 indices 3s, 3s+1, 3s+2 ; comp index = 4s + m/3 ; channel = m%3.
__global__ __launch_bounds__(256)
void k_main(const float* __restrict__ coeff, float* __restrict__ out, int n)
{
    const int lane = threadIdx.x & 31;
    const long wid = ((long)blockIdx.x * blockDim.x + threadIdx.x) >> 5;
    const int p = lane >> 2;   // point in warp 0..7
    const int s = lane & 3;

    long pi = wid * 8 + p;
    if (pi >= n) pi = n - 1;

    const float4 A = d_pdata4[pi * 2 + 0];
    const float4 B = d_pdata4[pi * 2 + 1];
    const float gx = A.x, gy = A.y, gz = A.z;
    const float nx = A.w, ny = B.x, nz = B.y;
    const int oidx = __float_as_int(B.z);

    const int ix = min((int)gx, RES - 2);
    const int iy = min((int)gy, RES - 2);
    const int iz = min((int)gz, RES - 2);
    const float fx = gx - (float)ix;
    const float fy = gy - (float)iy;
    const float fz = gz - (float)iz;
    const float ex = 1.0f - fx, ey = 1.0f - fy, ez = 1.0f - fz;

    // base: corner (0,0,0), this lane's first float4 (3s)
    const long cell0 = (((long)ix * RES) + iy) * RES + iz;
    const float4* b4 = (const float4*)(coeff + cell0 * 48) + 3 * s;

    float wv[12];
    #pragma unroll
    for (int k = 0; k < 12; k++) wv[k] = 0.0f;

    #pragma unroll
    for (int rd = 0; rd < 8; rd++) {
        const int dx = (rd >> 2) & 1, dy = (rd >> 1) & 1, dz = rd & 1;
        const float4* c4 = b4 + (dx * (RES * RES * 12) + dy * (RES * 12) + dz * 12);
        float4 v0 = __ldg(c4 + 0);
        float4 v1 = __ldg(c4 + 1);
        float4 v2 = __ldg(c4 + 2);
        const float w = (dx ? fx : ex) * (dy ? fy : ey) * (dz ? fz : ez);
        wv[0]  = fmaf(w, v0.x, wv[0]);  wv[1]  = fmaf(w, v0.y, wv[1]);
        wv[2]  = fmaf(w, v0.z, wv[2]);  wv[3]  = fmaf(w, v0.w, wv[3]);
        wv[4]  = fmaf(w, v1.x, wv[4]);  wv[5]  = fmaf(w, v1.y, wv[5]);
        wv[6]  = fmaf(w, v1.z, wv[6]);  wv[7]  = fmaf(w, v1.w, wv[7]);
        wv[8]  = fmaf(w, v2.x, wv[8]);  wv[9]  = fmaf(w, v2.y, wv[9]);
        wv[10] = fmaf(w, v2.z, wv[10]); wv[11] = fmaf(w, v2.w, wv[11]);
    }

    // SH components (degree 4), exact reference constants
    float comp[16];
    {
        const float x = nx, y = ny, z = nz;
        const float xx = x * x, yy = y * y, zz = z * z;
        const float xy = x * y, yz = y * z, xz = x * z;
        comp[0]  =  0.28209479177387814f;
        comp[1]  = -0.4886025119029199f * y;
        comp[2]  =  0.4886025119029199f * z;
        comp[3]  = -0.4886025119029199f * x;
        comp[4]  =  1.0925484305920792f * xy;
        comp[5]  = -1.0925484305920792f * yz;
        comp[6]  =  0.31539156525252005f * (2.0f * zz - xx - yy);
        comp[7]  = -1.0925484305920792f * xz;
        comp[8]  =  0.5462742152960396f * (xx - yy);
        comp[9]  = -0.5900435899266435f * y * (3.0f * xx - yy);
        comp[10] =  2.890611442640554f  * xy * z;
        comp[11] = -0.4570457994644658f * y * (4.0f * zz - xx - yy);
        comp[12] =  0.3731763325901154f * z * (2.0f * zz - 3.0f * xx - 3.0f * yy);
        comp[13] = -0.4570457994644658f * x * (4.0f * zz - xx - yy);
        comp[14] =  1.445305721320277f  * z * (xx - yy);
        comp[15] = -0.5900435899266435f * x * (xx - 3.0f * yy);
    }

    // per-lane coefficients comp[4s + t], via selects (no dynamic indexing)
    const float cc0 = (s == 0) ? comp[0]  : (s == 1) ? comp[4]  : (s == 2) ? comp[8]  : comp[12];
    const float cc1 = (s == 0) ? comp[1]  : (s == 1) ? comp[5]  : (s == 2) ? comp[9]  : comp[13];
    const float cc2 = (s == 0) ? comp[2]  : (s == 1) ? comp[6]  : (s == 2) ? comp[10] : comp[14];
    const float cc3 = (s == 0) ? comp[3]  : (s == 1) ? comp[7]  : (s == 2) ? comp[11] : comp[15];

    float p0, p1, p2;
    p0 = cc0 * wv[0];              p1 = cc0 * wv[1];              p2 = cc0 * wv[2];
    p0 = fmaf(cc1, wv[3], p0);     p1 = fmaf(cc1, wv[4], p1);     p2 = fmaf(cc1, wv[5], p2);
    p0 = fmaf(cc2, wv[6], p0);     p1 = fmaf(cc2, wv[7], p1);     p2 = fmaf(cc2, wv[8], p2);
    p0 = fmaf(cc3, wv[9], p0);     p1 = fmaf(cc3, wv[10], p1);    p2 = fmaf(cc3, wv[11], p2);

    // reduce over the 4 s-lanes of each point
    p0 += __shfl_xor_sync(0xffffffffu, p0, 1);
    p0 += __shfl_xor_sync(0xffffffffu, p0, 2);
    p1 += __shfl_xor_sync(0xffffffffu, p1, 1);
    p1 += __shfl_xor_sync(0xffffffffu, p1, 2);
    p2 += __shfl_xor_sync(0xffffffffu, p2, 1);
    p2 += __shfl_xor_sync(0xffffffffu, p2, 2);

    if (s < 3) {
        float v = (s == 0) ? p0 : (s == 1) ? p1 : p2;
        out[3 * (long)oidx + s] = fmaxf(v, 0.0f);
    }
}

extern "C" void kernel_launch(void* const* d_in, const int* in_sizes, int n_in,
                              void* d_out, int out_size)
{
    const float* coeff   = (const float*)d_in[0];
    const float* aabb    = (const float*)d_in[1];
    const float* points  = (const float*)d_in[2];
    const float* normals = (const float*)d_in[3];
    float* out = (float*)d_out;

    int n = in_sizes[2] / 3;

    k_setup<<<1, 32>>>(aabb);
    k_zero<<<NPTS_MAX / 256, 256>>>();
    k_hist<<<(n + 255) / 256, 256>>>(points, n);
    k_scan1<<<2048, 256>>>();
    k_scan2<<<1, 256>>>();
    k_scatter<<<(n + 255) / 256, 256>>>(points, normals, n);

    long warps = (n + 7) / 8;                 // 8 points per warp
    long threads = warps * 32;
    int block = 256;
    long grid = (threads + block - 1) / block;
    k_main<<<(int)grid, block>>>(coeff, out, n);
}

// round 8
// speedup vs baseline: 4.7935x; 1.0231x over previous
#include <cuda_runtime.h>

#define RES 128
#define NPTS_MAX 2097152

// ---------------- static scratch ----------------
__device__ float  d_params[6];
__device__ int    d_hist[NPTS_MAX];
__device__ int    d_btot[2048];
__device__ int    d_bsumx[2048];
__device__ int    d_cellid[NPTS_MAX];
__device__ float4 d_pdata4[NPTS_MAX * 2];   // sorted: {gx,gy,gz,nx},{ny,nz,idx,0}

__global__ void k_setup(const float* __restrict__ aabb)
{
    if (blockIdx.x == 0 && threadIdx.x == 0) {
        #pragma unroll
        for (int d = 0; d < 3; d++) {
            float amin = aabb[d], amax = aabb[d + 3];
            float s = 127.0f / (amax - amin);
            d_params[d]     = s;
            d_params[3 + d] = -amin * s;
        }
    }
}

__global__ void k_zero()
{
    int i = blockIdx.x * blockDim.x + threadIdx.x;
    if (i < NPTS_MAX) d_hist[i] = 0;
}

__global__ void k_hist(const float* __restrict__ points, int n)
{
    int i = blockIdx.x * blockDim.x + threadIdx.x;
    if (i >= n) return;
    float sx = d_params[0], sy = d_params[1], sz = d_params[2];
    float ox = d_params[3], oy = d_params[4], oz = d_params[5];
    float gx = fminf(fmaxf(fmaf(points[3 * i + 0], sx, ox), 0.0f), 127.0f);
    float gy = fminf(fmaxf(fmaf(points[3 * i + 1], sy, oy), 0.0f), 127.0f);
    float gz = fminf(fmaxf(fmaf(points[3 * i + 2], sz, oz), 0.0f), 127.0f);
    int ix = min((int)gx, RES - 2);
    int iy = min((int)gy, RES - 2);
    int iz = min((int)gz, RES - 2);
    int cell = (ix << 14) | (iy << 7) | iz;
    d_cellid[i] = cell;
    atomicAdd(&d_hist[cell], 1);
}

__global__ void k_scan1()
{
    __shared__ int wsum[8];
    int tid = threadIdx.x;
    long base = (long)blockIdx.x * 1024 + tid * 4;
    int4 v = *(int4*)&d_hist[base];
    int t = v.x + v.y + v.z + v.w;
    int lane = tid & 31, wp = tid >> 5;
    int sc = t;
    #pragma unroll
    for (int off = 1; off < 32; off <<= 1) {
        int nv = __shfl_up_sync(0xffffffffu, sc, off);
        if (lane >= off) sc += nv;
    }
    if (lane == 31) wsum[wp] = sc;
    __syncthreads();
    if (tid < 8) {
        int ws = wsum[tid];
        #pragma unroll
        for (int off = 1; off < 8; off <<= 1) {
            int nv = __shfl_up_sync(0x000000ffu, ws, off);
            if (tid >= off) ws += nv;
        }
        wsum[tid] = ws;
    }
    __syncthreads();
    int excl = sc - t + (wp ? wsum[wp - 1] : 0);
    int4 o;
    o.x = excl; o.y = o.x + v.x; o.z = o.y + v.y; o.w = o.z + v.z;
    *(int4*)&d_hist[base] = o;
    if (tid == 255) d_btot[blockIdx.x] = excl + t;
}

__global__ void k_scan2()
{
    __shared__ int wsum[8];
    int tid = threadIdx.x;
    int base = tid * 8;
    int v[8]; int t = 0;
    #pragma unroll
    for (int k = 0; k < 8; k++) { v[k] = d_btot[base + k]; t += v[k]; }
    int lane = tid & 31, wp = tid >> 5;
    int sc = t;
    #pragma unroll
    for (int off = 1; off < 32; off <<= 1) {
        int nv = __shfl_up_sync(0xffffffffu, sc, off);
        if (lane >= off) sc += nv;
    }
    if (lane == 31) wsum[wp] = sc;
    __syncthreads();
    if (tid < 8) {
        int ws = wsum[tid];
        #pragma unroll
        for (int off = 1; off < 8; off <<= 1) {
            int nv = __shfl_up_sync(0x000000ffu, ws, off);
            if (tid >= off) ws += nv;
        }
        wsum[tid] = ws;
    }
    __syncthreads();
    int run = sc - t + (wp ? wsum[wp - 1] : 0);
    #pragma unroll
    for (int k = 0; k < 8; k++) { d_bsumx[base + k] = run; run += v[k]; }
}

__global__ void k_scatter(const float* __restrict__ points,
                          const float* __restrict__ normals, int n)
{
    int i = blockIdx.x * blockDim.x + threadIdx.x;
    if (i >= n) return;
    int cell = d_cellid[i];
    int pos = atomicAdd(&d_hist[cell], 1) + __ldg(&d_bsumx[cell >> 10]);
    float sx = d_params[0], sy = d_params[1], sz = d_params[2];
    float ox = d_params[3], oy = d_params[4], oz = d_params[5];
    float4 A, B;
    A.x = fminf(fmaxf(fmaf(points[3 * i + 0], sx, ox), 0.0f), 127.0f);
    A.y = fminf(fmaxf(fmaf(points[3 * i + 1], sy, oy), 0.0f), 127.0f);
    A.z = fminf(fmaxf(fmaf(points[3 * i + 2], sz, oz), 0.0f), 127.0f);
    A.w = normals[3 * i + 0];
    B.x = normals[3 * i + 1]; B.y = normals[3 * i + 2];
    B.z = __int_as_float(i);  B.w = 0.0f;
    d_pdata4[(long)pos * 2 + 0] = A;
    d_pdata4[(long)pos * 2 + 1] = B;
}

// ---------------- main: 8 points/warp, interleaved loads + class rotation ----------
// lane = 4p + s. Element: reg j (0..2), comp q (0..3) <-> cell float F = 16j+4s+q.
//   comp index = F/3 (per-lane select), channel = (j+q+s)%3 = (class + s)%3,
//   class = (j+q)%3 -> accumulate A[class], rotate at the end.
__global__ __launch_bounds__(256)
void k_main(const float* __restrict__ coeff, float* __restrict__ out, int n)
{
    const int lane = threadIdx.x & 31;
    const long wid = ((long)blockIdx.x * blockDim.x + threadIdx.x) >> 5;
    const int p = lane >> 2;   // point in warp 0..7
    const int s = lane & 3;

    long pi = wid * 8 + p;
    if (pi >= n) pi = n - 1;

    const float4 A4 = d_pdata4[pi * 2 + 0];
    const float4 B4 = d_pdata4[pi * 2 + 1];
    const float gx = A4.x, gy = A4.y, gz = A4.z;
    const float nx = A4.w, ny = B4.x, nz = B4.y;
    const int oidx = __float_as_int(B4.z);

    const int ix = min((int)gx, RES - 2);
    const int iy = min((int)gy, RES - 2);
    const int iz = min((int)gz, RES - 2);
    const float fx = gx - (float)ix;
    const float fy = gy - (float)iy;
    const float fz = gz - (float)iz;
    const float ex = 1.0f - fx, ey = 1.0f - fy, ez = 1.0f - fz;

    // base: corner (0,0,0), interleaved sub-lane s
    const long cell0 = (((long)ix * RES) + iy) * RES + iz;
    const float4* b4 = (const float4*)(coeff + cell0 * 48) + s;

    float wv[12];
    #pragma unroll
    for (int k = 0; k < 12; k++) wv[k] = 0.0f;

    #pragma unroll
    for (int rd = 0; rd < 8; rd++) {
        const int dx = (rd >> 2) & 1, dy = (rd >> 1) & 1, dz = rd & 1;
        const float4* c4 = b4 + (dx * (RES * RES * 12) + dy * (RES * 12) + dz * 12);
        float4 v0 = __ldg(c4 + 0);   // floats 16*0 + 4s + q
        float4 v1 = __ldg(c4 + 4);   // floats 16*1 + 4s + q
        float4 v2 = __ldg(c4 + 8);   // floats 16*2 + 4s + q
        const float w = (dx ? fx : ex) * (dy ? fy : ey) * (dz ? fz : ez);
        wv[0]  = fmaf(w, v0.x, wv[0]);  wv[1]  = fmaf(w, v0.y, wv[1]);
        wv[2]  = fmaf(w, v0.z, wv[2]);  wv[3]  = fmaf(w, v0.w, wv[3]);
        wv[4]  = fmaf(w, v1.x, wv[4]);  wv[5]  = fmaf(w, v1.y, wv[5]);
        wv[6]  = fmaf(w, v1.z, wv[6]);  wv[7]  = fmaf(w, v1.w, wv[7]);
        wv[8]  = fmaf(w, v2.x, wv[8]);  wv[9]  = fmaf(w, v2.y, wv[9]);
        wv[10] = fmaf(w, v2.z, wv[10]); wv[11] = fmaf(w, v2.w, wv[11]);
    }

    // SH components (degree 4), exact reference constants
    float comp[16];
    {
        const float x = nx, y = ny, z = nz;
        const float xx = x * x, yy = y * y, zz = z * z;
        const float xy = x * y, yz = y * z, xz = x * z;
        comp[0]  =  0.28209479177387814f;
        comp[1]  = -0.4886025119029199f * y;
        comp[2]  =  0.4886025119029199f * z;
        comp[3]  = -0.4886025119029199f * x;
        comp[4]  =  1.0925484305920792f * xy;
        comp[5]  = -1.0925484305920792f * yz;
        comp[6]  =  0.31539156525252005f * (2.0f * zz - xx - yy);
        comp[7]  = -1.0925484305920792f * xz;
        comp[8]  =  0.5462742152960396f * (xx - yy);
        comp[9]  = -0.5900435899266435f * y * (3.0f * xx - yy);
        comp[10] =  2.890611442640554f  * xy * z;
        comp[11] = -0.4570457994644658f * y * (4.0f * zz - xx - yy);
        comp[12] =  0.3731763325901154f * z * (2.0f * zz - 3.0f * xx - 3.0f * yy);
        comp[13] = -0.4570457994644658f * x * (4.0f * zz - xx - yy);
        comp[14] =  1.445305721320277f  * z * (xx - yy);
        comp[15] = -0.5900435899266435f * x * (xx - 3.0f * yy);
    }

    // accumulate by class c = (j+q)%3 with per-lane comp[(16j+4s+q)/3]
    float A0 = 0.0f, A1 = 0.0f, A2 = 0.0f;
    #pragma unroll
    for (int j = 0; j < 3; j++) {
        #pragma unroll
        for (int q = 0; q < 4; q++) {
            const int base = 16 * j + q;
            // 4-way select over s (compile-time indices)
            const float cc = (s == 0) ? comp[(base + 0)  / 3]
                            : (s == 1) ? comp[(base + 4)  / 3]
                            : (s == 2) ? comp[(base + 8)  / 3]
                                       : comp[(base + 12) / 3];
            const float val = wv[4 * j + q];
            const int c = (j + q) % 3;
            if (c == 0)      A0 = fmaf(cc, val, A0);
            else if (c == 1) A1 = fmaf(cc, val, A1);
            else             A2 = fmaf(cc, val, A2);
        }
    }

    // rotate: channel of A[c] is (c+s)%3 -> B[ch] = A[(ch-s) mod 3]
    float B0, B1, B2;
    if (s == 1)      { B0 = A2; B1 = A0; B2 = A1; }
    else if (s == 2) { B0 = A1; B1 = A2; B2 = A0; }
    else             { B0 = A0; B1 = A1; B2 = A2; }   // s==0 or s==3

    // reduce over the 4 s-lanes of each point
    B0 += __shfl_xor_sync(0xffffffffu, B0, 1);
    B0 += __shfl_xor_sync(0xffffffffu, B0, 2);
    B1 += __shfl_xor_sync(0xffffffffu, B1, 1);
    B1 += __shfl_xor_sync(0xffffffffu, B1, 2);
    B2 += __shfl_xor_sync(0xffffffffu, B2, 1);
    B2 += __shfl_xor_sync(0xffffffffu, B2, 2);

    if (s < 3) {
        float v = (s == 0) ? B0 : (s == 1) ? B1 : B2;
        out[3 * (long)oidx + s] = fmaxf(v, 0.0f);
    }
}

extern "C" void kernel_launch(void* const* d_in, const int* in_sizes, int n_in,
                              void* d_out, int out_size)
{
    const float* coeff   = (const float*)d_in[0];
    const float* aabb    = (const float*)d_in[1];
    const float* points  = (const float*)d_in[2];
    const float* normals = (const float*)d_in[3];
    float* out = (float*)d_out;

    int n = in_sizes[2] / 3;

    k_setup<<<1, 32>>>(aabb);
    k_zero<<<NPTS_MAX / 256, 256>>>();
    k_hist<<<(n + 255) / 256, 256>>>(points, n);
    k_scan1<<<2048, 256>>>();
    k_scan2<<<1, 256>>>();
    k_scatter<<<(n + 255) / 256, 256>>>(points, normals, n);

    long warps = (n + 7) / 8;                 // 8 points per warp
    long threads = warps * 32;
    int block = 256;
    long grid = (threads + block - 1) / block;
    k_main<<<(int)grid, block>>>(coeff, out, n);
}